// round 2
// baseline (speedup 1.0000x reference)
#include <cuda_runtime.h>

// ---------------- problem constants ----------------
#define B_   4
#define L_   4096
#define D_   1024
#define H_   16
#define BS_  64
#define HD_  64
#define NB_  64
#define M_   (B_*L_)      // 16384 rows
#define BH_  (B_*H_)      // 64
#define QKVROW_ 3072      // 3*D

__device__ __constant__ float kSCALE   = 0.125f;          // HD^-0.5
__device__ __constant__ float kINVTEMP = 1.0f/0.7f;

// ---------------- scratch (device globals; no runtime alloc) ----------------
__device__ float g_qkv[M_ * QKVROW_];                 // [B,L,3D]   201 MB
__device__ float g_qr [BH_ * NB_ * HD_];              // block means
__device__ float g_kr [BH_ * NB_ * HD_];
__device__ float g_P  [BH_ * NB_ * NB_];              // sinkhorn perm
__device__ float g_ks [BH_ * NB_ * BS_ * HD_];        // sorted K  67 MB
__device__ float g_vs [BH_ * NB_ * BS_ * HD_];        // sorted V  67 MB
__device__ float g_ctx[M_ * D_];                      // attention out 67 MB

// ---------------- packed f32x2 helpers (sm_100+ PTX; SASS FFMA2) ----------------
__device__ __forceinline__ unsigned long long ffma2(unsigned long long a,
                                                    unsigned long long b,
                                                    unsigned long long c)
{
    unsigned long long d;
    asm("fma.rn.f32x2 %0, %1, %2, %3;" : "=l"(d) : "l"(a), "l"(b), "l"(c));
    return d;
}
__device__ __forceinline__ unsigned long long pack2(float x, float y)
{
    unsigned long long d;
    asm("mov.b64 %0, {%1, %2};" : "=l"(d) : "f"(x), "f"(y));
    return d;
}
__device__ __forceinline__ float2 unpack2(unsigned long long v)
{
    float2 r;
    asm("mov.b64 {%0, %1}, %2;" : "=f"(r.x), "=f"(r.y) : "l"(v));
    return r;
}

// =====================================================================
// 1) SGEMM + bias: C[M,N] = A[M,K] @ B[K,N] + bias[N]
//    128x128x8 tile, 256 threads, 8x8 micro-tile computed as 8x4 FFMA2.
//    A stored DUPLICATED in smem ({a,a} pairs) so the dup operand is a
//    single LDS.128; B pairs are contiguous (cols 2tx+32p, +1) -> LDS.64
//    conflict-free. Double-buffered, register-prefetch, 1 bar/ktile.
//    All dims multiples of 128/8 here -> no bounds checks.
// =====================================================================
__global__ __launch_bounds__(256, 2) void sgemm_bias(
    int M, int N, int K,
    const float* __restrict__ A, const float* __restrict__ Bm,
    const float* __restrict__ bias, float* __restrict__ C)
{
    __shared__ __align__(16) float As2[2][8][256];   // duplicated pairs: [k][2m],[2m+1]
    __shared__ __align__(16) float Bs [2][8][128];

    const int tid  = threadIdx.x;
    const int crow = blockIdx.y * 128;
    const int ccol = blockIdx.x * 128;
    const int arow = tid >> 1, acol4 = (tid & 1) * 4;
    const int brow = tid >> 5, bcol4 = (tid & 31) * 4;
    const int tx = tid & 15, ty = tid >> 4;

    const float* Ag = A  + (size_t)(crow + arow) * K + acol4;
    const float* Bg = Bm + (size_t)brow * N + ccol + bcol4;

    unsigned long long acc2[8][4];
    #pragma unroll
    for (int i = 0; i < 8; i++)
        #pragma unroll
        for (int p = 0; p < 4; p++) acc2[i][p] = 0ULL;

    // ---- preload tile 0 into buffer 0 ----
    float4 av = *(const float4*)(Ag);
    float4 bv = *(const float4*)(Bg);
    {
        float va[4] = {av.x, av.y, av.z, av.w};
        #pragma unroll
        for (int q = 0; q < 4; q++)
            *(float2*)&As2[0][acol4 + q][2*arow] = make_float2(va[q], va[q]);
        *(float4*)&Bs[0][brow][bcol4] = bv;
    }
    __syncthreads();

    for (int k0 = 0; k0 < K; k0 += 8) {
        const int buf = (k0 >> 3) & 1;
        const bool more = (k0 + 8) < K;
        if (more) {
            av = *(const float4*)(Ag + k0 + 8);
            bv = *(const float4*)(Bg + (size_t)(k0 + 8) * N);
        }
        #pragma unroll
        for (int kk = 0; kk < 8; kk++) {
            // a: 4 x LDS.128 -> 8 duplicated pairs (rows ty*8 .. ty*8+7)
            unsigned long long ad[8];
            #pragma unroll
            for (int u = 0; u < 4; u++) {
                ulonglong2 t = *(const ulonglong2*)&As2[buf][kk][ty*16 + 4*u];
                ad[2*u]   = t.x;
                ad[2*u+1] = t.y;
            }
            // b: 4 x LDS.64, cols {2tx+32p, 2tx+32p+1}
            unsigned long long bp[4];
            #pragma unroll
            for (int p = 0; p < 4; p++)
                bp[p] = *(const unsigned long long*)&Bs[buf][kk][2*tx + 32*p];
            #pragma unroll
            for (int i = 0; i < 8; i++)
                #pragma unroll
                for (int p = 0; p < 4; p++)
                    acc2[i][p] = ffma2(ad[i], bp[p], acc2[i][p]);
        }
        if (more) {
            float va[4] = {av.x, av.y, av.z, av.w};
            #pragma unroll
            for (int q = 0; q < 4; q++)
                *(float2*)&As2[buf ^ 1][acol4 + q][2*arow] = make_float2(va[q], va[q]);
            *(float4*)&Bs[buf ^ 1][brow][bcol4] = bv;
        }
        __syncthreads();
    }

    #pragma unroll
    for (int i = 0; i < 8; i++) {
        const int row = crow + ty*8 + i;
        #pragma unroll
        for (int p = 0; p < 4; p++) {
            const int col = ccol + 2*tx + 32*p;
            float2 bb = *(const float2*)&bias[col];
            float2 r  = unpack2(acc2[i][p]);
            r.x += bb.x; r.y += bb.y;
            *(float2*)&C[(size_t)row * N + col] = r;
        }
    }
}

// =====================================================================
// 2) Block means: q_repr/k_repr[bh,n,d] = mean_s qkv[b, n*64+s, {0,1024}+h*64+d]
// grid (NB, BH), 64 threads (one per d) -> coalesced 256B rows
// =====================================================================
__global__ void repr_kernel()
{
    int n = blockIdx.x, bh = blockIdx.y;
    int b = bh >> 4, h = bh & 15;
    int d = threadIdx.x;
    const float* base = g_qkv + ((size_t)(b*L_ + n*BS_)) * QKVROW_ + h*64 + d;
    float sq = 0.f, sk = 0.f;
    #pragma unroll 8
    for (int s = 0; s < 64; s++) {
        sq += base[(size_t)s * QKVROW_];
        sk += base[(size_t)s * QKVROW_ + 1024];
    }
    g_qr[((size_t)bh*64 + n)*64 + d] = sq * (1.f/64.f);
    g_kr[((size_t)bh*64 + n)*64 + d] = sk * (1.f/64.f);
}

// =====================================================================
// 3) sim + gumbel + 7 Sinkhorn iterations + exp -> P.  One block per (b,h).
// =====================================================================
__global__ __launch_bounds__(256) void sinkhorn_kernel(const float* __restrict__ gumbel)
{
    __shared__ float sQ[64][65], sK[64][65], la[64][65];
    const int bh = blockIdx.x;
    const int tid = threadIdx.x;

    for (int f = tid; f < 1024; f += 256) {
        int r = f >> 4, c4 = (f & 15) * 4;
        float4 q = *(const float4*)&g_qr[((size_t)bh*64 + r)*64 + c4];
        float4 k = *(const float4*)&g_kr[((size_t)bh*64 + r)*64 + c4];
        sQ[r][c4]=q.x; sQ[r][c4+1]=q.y; sQ[r][c4+2]=q.z; sQ[r][c4+3]=q.w;
        sK[r][c4]=k.x; sK[r][c4+1]=k.y; sK[r][c4+2]=k.z; sK[r][c4+3]=k.w;
    }
    __syncthreads();

    const int tx = tid & 15, ty = tid >> 4;
    float acc[4][4] = {};
    for (int d = 0; d < 64; d++) {
        float ar[4], br[4];
        #pragma unroll
        for (int i = 0; i < 4; i++) ar[i] = sQ[ty*4+i][d];
        #pragma unroll
        for (int j = 0; j < 4; j++) br[j] = sK[tx*4+j][d];
        #pragma unroll
        for (int i = 0; i < 4; i++)
            #pragma unroll
            for (int j = 0; j < 4; j++)
                acc[i][j] += ar[i] * br[j];
    }
    #pragma unroll
    for (int i = 0; i < 4; i++)
        #pragma unroll
        for (int j = 0; j < 4; j++) {
            int r = ty*4+i, c = tx*4+j;
            float g = gumbel[((size_t)bh*64 + r)*64 + c];
            la[r][c] = (acc[i][j] * kSCALE + g) * kINVTEMP;
        }
    __syncthreads();

    const int warp = tid >> 5, lane = tid & 31;
    for (int it = 0; it < 7; it++) {
        // row normalization (axis=-1)
        for (int r = warp; r < 64; r += 8) {
            float a = la[r][lane], b = la[r][lane+32];
            float m = fmaxf(a, b);
            #pragma unroll
            for (int o = 16; o; o >>= 1) m = fmaxf(m, __shfl_xor_sync(0xffffffffu, m, o));
            float s = expf(a - m) + expf(b - m);
            #pragma unroll
            for (int o = 16; o; o >>= 1) s += __shfl_xor_sync(0xffffffffu, s, o);
            float lse = m + logf(s);
            la[r][lane] = a - lse; la[r][lane+32] = b - lse;
        }
        __syncthreads();
        // column normalization (axis=-2)
        for (int c = warp; c < 64; c += 8) {
            float a = la[lane][c], b = la[lane+32][c];
            float m = fmaxf(a, b);
            #pragma unroll
            for (int o = 16; o; o >>= 1) m = fmaxf(m, __shfl_xor_sync(0xffffffffu, m, o));
            float s = expf(a - m) + expf(b - m);
            #pragma unroll
            for (int o = 16; o; o >>= 1) s += __shfl_xor_sync(0xffffffffu, s, o);
            float lse = m + logf(s);
            la[lane][c] = a - lse; la[lane+32][c] = b - lse;
        }
        __syncthreads();
    }
    for (int f = tid; f < 4096; f += 256)
        g_P[(size_t)bh*4096 + f] = expf(la[f >> 6][f & 63]);
}

// =====================================================================
// 4) Soft block-sort: for each (bh, s-slice fc): out[n,d] = sum_m P[n,m]*KV[m,fc,d]
//    Reads each K/V element exactly once.  grid (fc=64, bh=64), 256 thr.
// =====================================================================
__global__ __launch_bounds__(256) void sort_kernel()
{
    __shared__ float sP[64][65], sK[64][68], sV[64][68];
    const int fc = blockIdx.x, bh = blockIdx.y;
    const int b = bh >> 4, h = bh & 15;
    const int tid = threadIdx.x;

    for (int f = tid; f < 1024; f += 256) {
        int r = f >> 4, c4 = (f & 15) * 4;
        float4 p = *(const float4*)&g_P[(size_t)bh*4096 + r*64 + c4];
        sP[r][c4]=p.x; sP[r][c4+1]=p.y; sP[r][c4+2]=p.z; sP[r][c4+3]=p.w;
        const float* src = g_qkv + ((size_t)(b*L_ + r*64 + fc)) * QKVROW_ + 1024 + h*64 + c4;
        float4 k = *(const float4*)src;
        sK[r][c4]=k.x; sK[r][c4+1]=k.y; sK[r][c4+2]=k.z; sK[r][c4+3]=k.w;
        float4 v = *(const float4*)(src + 1024);
        sV[r][c4]=v.x; sV[r][c4+1]=v.y; sV[r][c4+2]=v.z; sV[r][c4+3]=v.w;
    }
    __syncthreads();

    const int tx = tid & 15, ty = tid >> 4;
    float aK[4][4] = {}, aV[4][4] = {};
    for (int m = 0; m < 64; m++) {
        float p[4], kk[4], vv[4];
        #pragma unroll
        for (int i = 0; i < 4; i++) p[i] = sP[ty*4+i][m];
        #pragma unroll
        for (int j = 0; j < 4; j++) { kk[j] = sK[m][tx*4+j]; vv[j] = sV[m][tx*4+j]; }
        #pragma unroll
        for (int i = 0; i < 4; i++)
            #pragma unroll
            for (int j = 0; j < 4; j++) {
                aK[i][j] += p[i] * kk[j];
                aV[i][j] += p[i] * vv[j];
            }
    }
    #pragma unroll
    for (int i = 0; i < 4; i++) {
        int n = ty*4+i;
        size_t off = (((size_t)bh*64 + n)*64 + fc)*64 + tx*4;
        *(float4*)&g_ks[off] = make_float4(aK[i][0],aK[i][1],aK[i][2],aK[i][3]);
        *(float4*)&g_vs[off] = make_float4(aV[i][0],aV[i][1],aV[i][2],aV[i][3]);
    }
}

// =====================================================================
// 5) Local block attention. One block per (b,h,n).
//    K kept d-major in smem (sKt) so the QK^T inner loop is conflict-free.
// =====================================================================
__global__ __launch_bounds__(256) void attn_kernel()
{
    extern __shared__ float sm[];
    float (*sQ)[65]   = (float(*)[65])  sm;                                // 64x65
    float (*sKt)[132] = (float(*)[132]) (sm + 64*65);                      // 64(d) x 132(j)
    float (*sV)[64]   = (float(*)[64])  (sm + 64*65 + 64*132);             // 128 x 64
    float (*sS)[132]  = (float(*)[132]) (sm + 64*65 + 64*132 + 128*64);    // 64 x 132

    const int n = blockIdx.x, bh = blockIdx.y;
    const int b = bh >> 4, h = bh & 15;
    const int tid = threadIdx.x;
    const int n1 = (n + 1) & 63;

    for (int f = tid; f < 1024; f += 256) {
        int r = f >> 4, d4 = (f & 15) * 4;
        const float* src = g_qkv + ((size_t)(b*L_ + n*64 + r)) * QKVROW_ + h*64 + d4;
        float4 q = *(const float4*)src;
        sQ[r][d4]=q.x; sQ[r][d4+1]=q.y; sQ[r][d4+2]=q.z; sQ[r][d4+3]=q.w;
        float4 k = *(const float4*)(src + 1024);
        sKt[d4][r]=k.x; sKt[d4+1][r]=k.y; sKt[d4+2][r]=k.z; sKt[d4+3][r]=k.w;
        float4 v = *(const float4*)(src + 2048);
        sV[r][d4]=v.x; sV[r][d4+1]=v.y; sV[r][d4+2]=v.z; sV[r][d4+3]=v.w;
        size_t so = (((size_t)bh*64 + n1)*64 + r)*64 + d4;
        float4 k2 = *(const float4*)&g_ks[so];
        sKt[d4][64+r]=k2.x; sKt[d4+1][64+r]=k2.y; sKt[d4+2][64+r]=k2.z; sKt[d4+3][64+r]=k2.w;
        float4 v2 = *(const float4*)&g_vs[so];
        sV[64+r][d4]=v2.x; sV[64+r][d4+1]=v2.y; sV[64+r][d4+2]=v2.z; sV[64+r][d4+3]=v2.w;
    }
    __syncthreads();

    const int tx = tid & 15, ty = tid >> 4;
    // scores: q-tile 4 (ty), j-tile 8 (tx)
    float acc[4][8] = {};
    for (int d = 0; d < 64; d++) {
        float ar[4];
        #pragma unroll
        for (int i = 0; i < 4; i++) ar[i] = sQ[ty*4+i][d];
        float4 b0 = *(const float4*)&sKt[d][tx*8];
        float4 b1 = *(const float4*)&sKt[d][tx*8+4];
        float br[8] = {b0.x,b0.y,b0.z,b0.w,b1.x,b1.y,b1.z,b1.w};
        #pragma unroll
        for (int i = 0; i < 4; i++)
            #pragma unroll
            for (int j = 0; j < 8; j++)
                acc[i][j] += ar[i] * br[j];
    }
    const bool lastb = (n == NB_ - 1);
    #pragma unroll
    for (int i = 0; i < 4; i++)
        #pragma unroll
        for (int j = 0; j < 8; j++) {
            int q = ty*4+i, jj = tx*8+j;
            float v = acc[i][j] * kSCALE;
            if (lastb && jj >= 64) v = -1e9f;
            sS[q][jj] = v;
        }
    __syncthreads();

    // softmax over 128 keys, one warp handles 8 rows
    const int warp = tid >> 5, lane = tid & 31;
    for (int r = warp; r < 64; r += 8) {
        float x0=sS[r][lane], x1=sS[r][lane+32], x2=sS[r][lane+64], x3=sS[r][lane+96];
        float m = fmaxf(fmaxf(x0,x1), fmaxf(x2,x3));
        #pragma unroll
        for (int o = 16; o; o >>= 1) m = fmaxf(m, __shfl_xor_sync(0xffffffffu, m, o));
        float e0=expf(x0-m), e1=expf(x1-m), e2=expf(x2-m), e3=expf(x3-m);
        float s = e0+e1+e2+e3;
        #pragma unroll
        for (int o = 16; o; o >>= 1) s += __shfl_xor_sync(0xffffffffu, s, o);
        float inv = 1.f / s;
        sS[r][lane]=e0*inv; sS[r][lane+32]=e1*inv; sS[r][lane+64]=e2*inv; sS[r][lane+96]=e3*inv;
    }
    __syncthreads();

    // out = P @ V : q-tile 4 (ty), d-tile 4 (tx)
    float o[4][4] = {};
    for (int j = 0; j < 128; j++) {
        float p[4];
        #pragma unroll
        for (int i = 0; i < 4; i++) p[i] = sS[ty*4+i][j];
        float4 vv = *(const float4*)&sV[j][tx*4];
        float vr[4] = {vv.x, vv.y, vv.z, vv.w};
        #pragma unroll
        for (int i = 0; i < 4; i++)
            #pragma unroll
            for (int k = 0; k < 4; k++)
                o[i][k] += p[i] * vr[k];
    }
    #pragma unroll
    for (int i = 0; i < 4; i++) {
        int q = ty*4+i;
        size_t off = ((size_t)(b*L_ + n*64 + q)) * D_ + h*64 + tx*4;
        *(float4*)&g_ctx[off] = make_float4(o[i][0], o[i][1], o[i][2], o[i][3]);
    }
}

// =====================================================================
// launcher
// =====================================================================
extern "C" void kernel_launch(void* const* d_in, const int* in_sizes, int n_in,
                              void* d_out, int out_size)
{
    (void)in_sizes; (void)n_in; (void)out_size;
    const float* x      = (const float*)d_in[0];
    const float* gumbel = (const float*)d_in[1];
    const float* W_qkv  = (const float*)d_in[2];
    const float* b_qkv  = (const float*)d_in[3];
    const float* W_out  = (const float*)d_in[4];
    const float* b_out  = (const float*)d_in[5];
    float* out = (float*)d_out;

    float *qkv_p, *ctx_p;
    cudaGetSymbolAddress((void**)&qkv_p, g_qkv);
    cudaGetSymbolAddress((void**)&ctx_p, g_ctx);

    // 1) qkv projection: [16384,1024] @ [1024,3072] + b
    sgemm_bias<<<dim3(QKVROW_/128, M_/128), 256>>>(M_, QKVROW_, D_, x, W_qkv, b_qkv, qkv_p);
    // 2) block summaries
    repr_kernel<<<dim3(NB_, BH_), 64>>>();
    // 3) gumbel-sinkhorn permutation
    sinkhorn_kernel<<<BH_, 256>>>(gumbel);
    // 4) soft-sort K/V blocks
    sort_kernel<<<dim3(64, BH_), 256>>>();
    // 5) local attention
    int smem = (64*65 + 64*132 + 128*64 + 64*132) * (int)sizeof(float);
    cudaFuncSetAttribute(attn_kernel, cudaFuncAttributeMaxDynamicSharedMemorySize, smem);
    attn_kernel<<<dim3(NB_, BH_), 256, smem>>>();
    // 6) output projection: [16384,1024] @ [1024,1024] + b
    sgemm_bias<<<dim3(D_/128, M_/128), 256>>>(M_, D_, D_, ctx_p, W_out, b_out, out);
}

// round 8
// speedup vs baseline: 1.7540x; 1.7540x over previous
#include <cuda_runtime.h>
#include <cuda_bf16.h>
#include <cstdint>

// ---------------- problem constants ----------------
#define B_   4
#define L_   4096
#define D_   1024
#define H_   16
#define BS_  64
#define HD_  64
#define NB_  64
#define M_   (B_*L_)      // 16384 rows
#define BH_  (B_*H_)      // 64
#define QKVROW_ 3072      // 3*D
#define KDIM_ 1024

__device__ __constant__ float kSCALE   = 0.125f;          // HD^-0.5
__device__ __constant__ float kINVTEMP = 1.0f/0.7f;

// ---------------- scratch (device globals; no runtime alloc) ----------------
__device__ float g_qkv[M_ * QKVROW_];                 // [B,L,3D]   201 MB
__device__ float g_qr [BH_ * NB_ * HD_];
__device__ float g_kr [BH_ * NB_ * HD_];
__device__ float g_P  [BH_ * NB_ * NB_];
__device__ float g_ks [BH_ * NB_ * BS_ * HD_];        // sorted K
__device__ float g_vs [BH_ * NB_ * BS_ * HD_];        // sorted V
__device__ float g_ctx[M_ * D_];                      // attention out

// bf16 split operands (uint4-typed for guaranteed 16B alignment)
__device__ uint4 g_ah4 [M_ * KDIM_ / 8];              // x hi
__device__ uint4 g_al4 [M_ * KDIM_ / 8];              // x lo
__device__ uint4 g_ch4 [M_ * KDIM_ / 8];              // ctx hi
__device__ uint4 g_cl4 [M_ * KDIM_ / 8];              // ctx lo
__device__ uint4 g_bh4 [QKVROW_ * KDIM_ / 8];         // W_qkv^T hi
__device__ uint4 g_bl4 [QKVROW_ * KDIM_ / 8];         // W_qkv^T lo
__device__ uint4 g_b2h4[D_ * KDIM_ / 8];              // W_out^T hi
__device__ uint4 g_b2l4[D_ * KDIM_ / 8];              // W_out^T lo

// =====================================================================
// arch-portable helpers (sm_80+ features only: ldmatrix, mma.sync, cp.async)
// =====================================================================
__device__ __forceinline__ uint32_t smem_u32(const void* p) {
    uint32_t a;
    asm("{ .reg .u64 t; cvta.to.shared.u64 t, %1; cvt.u32.u64 %0, t; }" : "=r"(a) : "l"(p));
    return a;
}
__device__ __forceinline__ void ldsm_x4(uint32_t* r, uint32_t addr) {
    asm volatile("ldmatrix.sync.aligned.m8n8.x4.shared.b16 {%0,%1,%2,%3}, [%4];"
                 : "=r"(r[0]), "=r"(r[1]), "=r"(r[2]), "=r"(r[3]) : "r"(addr));
}
__device__ __forceinline__ void mma_bf16(float* d, const uint32_t* a, uint32_t b0, uint32_t b1) {
    asm volatile("mma.sync.aligned.m16n8k16.row.col.f32.bf16.bf16.f32 "
                 "{%0,%1,%2,%3}, {%4,%5,%6,%7}, {%8,%9}, {%0,%1,%2,%3};"
                 : "+f"(d[0]), "+f"(d[1]), "+f"(d[2]), "+f"(d[3])
                 : "r"(a[0]), "r"(a[1]), "r"(a[2]), "r"(a[3]), "r"(b0), "r"(b1));
}
__device__ __forceinline__ void cp_async16(uint32_t saddr, const void* gptr) {
    asm volatile("cp.async.cg.shared.global [%0], [%1], 16;" :: "r"(saddr), "l"(gptr));
}
#define CP_COMMIT()  asm volatile("cp.async.commit_group;" ::: "memory")
#define CP_WAIT(n)   asm volatile("cp.async.wait_group %0;" :: "n"(n) : "memory")

// =====================================================================
// split fp32 -> (hi, lo) bf16.  4 elems/thread, vectorized.
// =====================================================================
__global__ void split_kernel(const float4* __restrict__ src,
                             uint2* __restrict__ hi, uint2* __restrict__ lo, int n4)
{
    int i = blockIdx.x * blockDim.x + threadIdx.x;
    if (i >= n4) return;
    float4 v = src[i];
    float vv[4] = {v.x, v.y, v.z, v.w};
    uint32_t hh[4], ll[4];
    #pragma unroll
    for (int j = 0; j < 4; j++) {
        __nv_bfloat16 h = __float2bfloat16(vv[j]);
        __nv_bfloat16 l = __float2bfloat16(vv[j] - __bfloat162float(h));
        hh[j] = (uint32_t)__bfloat16_as_ushort(h);
        ll[j] = (uint32_t)__bfloat16_as_ushort(l);
    }
    hi[i] = make_uint2(hh[0] | (hh[1] << 16), hh[2] | (hh[3] << 16));
    lo[i] = make_uint2(ll[0] | (ll[1] << 16), ll[2] | (ll[3] << 16));
}

// =====================================================================
// transpose + split: W[K,N] fp32 -> Wt_hi/lo[N,K] bf16
// =====================================================================
__global__ void tsplit_kernel(const float* __restrict__ W,
                              __nv_bfloat16* __restrict__ Th, __nv_bfloat16* __restrict__ Tl,
                              int Kdim, int Ncols)
{
    __shared__ float s[32][33];
    int n0 = blockIdx.x * 32, k0 = blockIdx.y * 32;
    int tx = threadIdx.x, ty = threadIdx.y;          // 32 x 8
    #pragma unroll
    for (int j = 0; j < 4; j++)
        s[ty + 8*j][tx] = W[(size_t)(k0 + ty + 8*j) * Ncols + n0 + tx];
    __syncthreads();
    #pragma unroll
    for (int j = 0; j < 4; j++) {
        float v = s[tx][ty + 8*j];
        __nv_bfloat16 h = __float2bfloat16(v);
        __nv_bfloat16 l = __float2bfloat16(v - __bfloat162float(h));
        size_t o = (size_t)(n0 + ty + 8*j) * Kdim + k0 + tx;
        Th[o] = h; Tl[o] = l;
    }
}

// =====================================================================
// mma.sync split-bf16 GEMM: C[M,N] = A[M,1024] @ Bt[N,1024]^T + bias
// 128x128 CTA tile, 8 warps (warp tile 64x32), K-chunk 32, cp.async
// double-buffered. 3-term compensated: Ah*Bh + Ah*Bl + Al*Bh.
// smem per matrix tile: 128 rows x 80B pitch (32 bf16 + 8 pad) -> LDSM
// 16B-chunk pattern {0,80,32,112,64,16,96,48} mod 128 = conflict-free.
// =====================================================================
#define TILE_BYTES_  10240                 // 128 * 80
#define STAGE_BYTES_ 40960                 // 4 matrices
__global__ __launch_bounds__(256) void mma_gemm(
    const uint4* __restrict__ Ah4, const uint4* __restrict__ Al4,
    const uint4* __restrict__ Bh4, const uint4* __restrict__ Bl4,
    const float* __restrict__ bias, float* __restrict__ C, int N)
{
    extern __shared__ __align__(16) char smem[];
    const uint32_t sbase = smem_u32(smem);
    const int tid  = threadIdx.x;
    const int lane = tid & 31, wid = tid >> 5;
    const int wm = (wid & 1) * 64;        // warp row offset in tile
    const int wn = (wid >> 1) * 32;       // warp col offset in tile
    const int m0 = blockIdx.y * 128;
    const int n0 = blockIdx.x * 128;

    float acc[4][4][4] = {};              // [mt][nt][frag]

    // ---- stage issue: 2048 x 16B chunks, 8 per thread ----
    // t>>1 selects matrix (Ah,Al,Bh,Bl); rem = row*4 + 16B-chunk within row
    #define ISSUE_STAGE(S, BUF) do {                                          \
        uint32_t sb_ = sbase + (BUF) * STAGE_BYTES_;                          \
        _Pragma("unroll")                                                     \
        for (int t = 0; t < 8; t++) {                                         \
            const int mtx = t >> 1;                                           \
            int rem = tid + (t & 1) * 256;                                    \
            int row = rem >> 2, c = rem & 3;                                  \
            const uint4* src = (mtx == 0) ? Ah4 : (mtx == 1) ? Al4            \
                             : (mtx == 2) ? Bh4 : Bl4;                        \
            int rb = (mtx < 2) ? m0 : n0;                                     \
            cp_async16(sb_ + mtx * TILE_BYTES_ + row * 80 + c * 16,           \
                       src + (size_t)(rb + row) * 128 + (S) * 4 + c);         \
        }                                                                     \
        CP_COMMIT();                                                          \
    } while (0)

    ISSUE_STAGE(0, 0);

    for (int s = 0; s < 32; s++) {
        const int buf = s & 1;
        if (s + 1 < 32) { ISSUE_STAGE(s + 1, buf ^ 1); CP_WAIT(1); }
        else            { CP_WAIT(0); }
        __syncthreads();

        const uint32_t sb = sbase + buf * STAGE_BYTES_;
        #pragma unroll
        for (int kt = 0; kt < 2; kt++) {
            const uint32_t lrow = (uint32_t)(lane & 15);
            const uint32_t lcolB = (uint32_t)(kt * 16 + ((lane >> 4) << 3)) * 2;  // bytes
            uint32_t Ahf[4][4], Alf[4][4];
            #pragma unroll
            for (int mt = 0; mt < 4; mt++) {
                uint32_t off = (wm + mt * 16 + lrow) * 80 + lcolB;
                ldsm_x4(Ahf[mt], sb + 0 * TILE_BYTES_ + off);
                ldsm_x4(Alf[mt], sb + 1 * TILE_BYTES_ + off);
            }
            uint32_t Bhf[2][4], Blf[2][4];
            #pragma unroll
            for (int np = 0; np < 2; np++) {
                uint32_t off = (wn + np * 16 + lrow) * 80 + lcolB;
                ldsm_x4(Bhf[np], sb + 2 * TILE_BYTES_ + off);
                ldsm_x4(Blf[np], sb + 3 * TILE_BYTES_ + off);
            }
            #pragma unroll
            for (int mt = 0; mt < 4; mt++)
                #pragma unroll
                for (int nt = 0; nt < 4; nt++) {
                    const int np = nt >> 1, hi = nt & 1;
                    mma_bf16(acc[mt][nt], Ahf[mt], Bhf[np][hi], Bhf[np][hi + 2]);
                    mma_bf16(acc[mt][nt], Ahf[mt], Blf[np][hi], Blf[np][hi + 2]);
                    mma_bf16(acc[mt][nt], Alf[mt], Bhf[np][hi], Bhf[np][hi + 2]);
                }
        }
        __syncthreads();
    }

    // ---- epilogue: fragment -> global + bias ----
    #pragma unroll
    for (int mt = 0; mt < 4; mt++)
        #pragma unroll
        for (int nt = 0; nt < 4; nt++) {
            int row = m0 + wm + mt * 16 + (lane >> 2);
            int col = n0 + wn + nt * 8 + 2 * (lane & 3);
            float2 b2 = *(const float2*)&bias[col];
            float2 o0 = make_float2(acc[mt][nt][0] + b2.x, acc[mt][nt][1] + b2.y);
            float2 o1 = make_float2(acc[mt][nt][2] + b2.x, acc[mt][nt][3] + b2.y);
            *(float2*)&C[(size_t)row * N + col]       = o0;
            *(float2*)&C[(size_t)(row + 8) * N + col] = o1;
        }
}

// =====================================================================
// 2) Block means
// =====================================================================
__global__ void repr_kernel()
{
    int n = blockIdx.x, bh = blockIdx.y;
    int b = bh >> 4, h = bh & 15;
    int d = threadIdx.x;
    const float* base = g_qkv + ((size_t)(b*L_ + n*BS_)) * QKVROW_ + h*64 + d;
    float sq = 0.f, sk = 0.f;
    #pragma unroll 8
    for (int s = 0; s < 64; s++) {
        sq += base[(size_t)s * QKVROW_];
        sk += base[(size_t)s * QKVROW_ + 1024];
    }
    g_qr[((size_t)bh*64 + n)*64 + d] = sq * (1.f/64.f);
    g_kr[((size_t)bh*64 + n)*64 + d] = sk * (1.f/64.f);
}

// =====================================================================
// 3) sim + gumbel + 7 Sinkhorn iterations + exp -> P
// =====================================================================
__global__ __launch_bounds__(256) void sinkhorn_kernel(const float* __restrict__ gumbel)
{
    __shared__ float sQ[64][65], sK[64][65], la[64][65];
    const int bh = blockIdx.x;
    const int tid = threadIdx.x;

    for (int f = tid; f < 1024; f += 256) {
        int r = f >> 4, c4 = (f & 15) * 4;
        float4 q = *(const float4*)&g_qr[((size_t)bh*64 + r)*64 + c4];
        float4 k = *(const float4*)&g_kr[((size_t)bh*64 + r)*64 + c4];
        sQ[r][c4]=q.x; sQ[r][c4+1]=q.y; sQ[r][c4+2]=q.z; sQ[r][c4+3]=q.w;
        sK[r][c4]=k.x; sK[r][c4+1]=k.y; sK[r][c4+2]=k.z; sK[r][c4+3]=k.w;
    }
    __syncthreads();

    const int tx = tid & 15, ty = tid >> 4;
    float acc[4][4] = {};
    for (int d = 0; d < 64; d++) {
        float ar[4], br[4];
        #pragma unroll
        for (int i = 0; i < 4; i++) ar[i] = sQ[ty*4+i][d];
        #pragma unroll
        for (int j = 0; j < 4; j++) br[j] = sK[tx*4+j][d];
        #pragma unroll
        for (int i = 0; i < 4; i++)
            #pragma unroll
            for (int j = 0; j < 4; j++)
                acc[i][j] += ar[i] * br[j];
    }
    #pragma unroll
    for (int i = 0; i < 4; i++)
        #pragma unroll
        for (int j = 0; j < 4; j++) {
            int r = ty*4+i, c = tx*4+j;
            float g = gumbel[((size_t)bh*64 + r)*64 + c];
            la[r][c] = (acc[i][j] * kSCALE + g) * kINVTEMP;
        }
    __syncthreads();

    const int warp = tid >> 5, lane = tid & 31;
    for (int it = 0; it < 7; it++) {
        for (int r = warp; r < 64; r += 8) {
            float a = la[r][lane], b = la[r][lane+32];
            float m = fmaxf(a, b);
            #pragma unroll
            for (int o = 16; o; o >>= 1) m = fmaxf(m, __shfl_xor_sync(0xffffffffu, m, o));
            float s = expf(a - m) + expf(b - m);
            #pragma unroll
            for (int o = 16; o; o >>= 1) s += __shfl_xor_sync(0xffffffffu, s, o);
            float lse = m + logf(s);
            la[r][lane] = a - lse; la[r][lane+32] = b - lse;
        }
        __syncthreads();
        for (int c = warp; c < 64; c += 8) {
            float a = la[lane][c], b = la[lane+32][c];
            float m = fmaxf(a, b);
            #pragma unroll
            for (int o = 16; o; o >>= 1) m = fmaxf(m, __shfl_xor_sync(0xffffffffu, m, o));
            float s = expf(a - m) + expf(b - m);
            #pragma unroll
            for (int o = 16; o; o >>= 1) s += __shfl_xor_sync(0xffffffffu, s, o);
            float lse = m + logf(s);
            la[lane][c] = a - lse; la[lane+32][c] = b - lse;
        }
        __syncthreads();
    }
    for (int f = tid; f < 4096; f += 256)
        g_P[(size_t)bh*4096 + f] = expf(la[f >> 6][f & 63]);
}

// =====================================================================
// 4) Soft block-sort
// =====================================================================
__global__ __launch_bounds__(256) void sort_kernel()
{
    __shared__ float sP[64][65], sK[64][68], sV[64][68];
    const int fc = blockIdx.x, bh = blockIdx.y;
    const int b = bh >> 4, h = bh & 15;
    const int tid = threadIdx.x;

    for (int f = tid; f < 1024; f += 256) {
        int r = f >> 4, c4 = (f & 15) * 4;
        float4 p = *(const float4*)&g_P[(size_t)bh*4096 + r*64 + c4];
        sP[r][c4]=p.x; sP[r][c4+1]=p.y; sP[r][c4+2]=p.z; sP[r][c4+3]=p.w;
        const float* src = g_qkv + ((size_t)(b*L_ + r*64 + fc)) * QKVROW_ + 1024 + h*64 + c4;
        float4 k = *(const float4*)src;
        sK[r][c4]=k.x; sK[r][c4+1]=k.y; sK[r][c4+2]=k.z; sK[r][c4+3]=k.w;
        float4 v = *(const float4*)(src + 1024);
        sV[r][c4]=v.x; sV[r][c4+1]=v.y; sV[r][c4+2]=v.z; sV[r][c4+3]=v.w;
    }
    __syncthreads();

    const int tx = tid & 15, ty = tid >> 4;
    float aK[4][4] = {}, aV[4][4] = {};
    for (int m = 0; m < 64; m++) {
        float p[4], kk[4], vv[4];
        #pragma unroll
        for (int i = 0; i < 4; i++) p[i] = sP[ty*4+i][m];
        #pragma unroll
        for (int j = 0; j < 4; j++) { kk[j] = sK[m][tx*4+j]; vv[j] = sV[m][tx*4+j]; }
        #pragma unroll
        for (int i = 0; i < 4; i++)
            #pragma unroll
            for (int j = 0; j < 4; j++) {
                aK[i][j] += p[i] * kk[j];
                aV[i][j] += p[i] * vv[j];
            }
    }
    #pragma unroll
    for (int i = 0; i < 4; i++) {
        int n = ty*4+i;
        size_t off = (((size_t)bh*64 + n)*64 + fc)*64 + tx*4;
        *(float4*)&g_ks[off] = make_float4(aK[i][0],aK[i][1],aK[i][2],aK[i][3]);
        *(float4*)&g_vs[off] = make_float4(aV[i][0],aV[i][1],aV[i][2],aV[i][3]);
    }
}

// =====================================================================
// 5) Local block attention
// =====================================================================
__global__ __launch_bounds__(256) void attn_kernel()
{
    extern __shared__ float sm[];
    float (*sQ)[65]   = (float(*)[65])  sm;
    float (*sKt)[132] = (float(*)[132]) (sm + 64*65);
    float (*sV)[64]   = (float(*)[64])  (sm + 64*65 + 64*132);
    float (*sS)[132]  = (float(*)[132]) (sm + 64*65 + 64*132 + 128*64);

    const int n = blockIdx.x, bh = blockIdx.y;
    const int b = bh >> 4, h = bh & 15;
    const int tid = threadIdx.x;
    const int n1 = (n + 1) & 63;

    for (int f = tid; f < 1024; f += 256) {
        int r = f >> 4, d4 = (f & 15) * 4;
        const float* src = g_qkv + ((size_t)(b*L_ + n*64 + r)) * QKVROW_ + h*64 + d4;
        float4 q = *(const float4*)src;
        sQ[r][d4]=q.x; sQ[r][d4+1]=q.y; sQ[r][d4+2]=q.z; sQ[r][d4+3]=q.w;
        float4 k = *(const float4*)(src + 1024);
        sKt[d4][r]=k.x; sKt[d4+1][r]=k.y; sKt[d4+2][r]=k.z; sKt[d4+3][r]=k.w;
        float4 v = *(const float4*)(src + 2048);
        sV[r][d4]=v.x; sV[r][d4+1]=v.y; sV[r][d4+2]=v.z; sV[r][d4+3]=v.w;
        size_t so = (((size_t)bh*64 + n1)*64 + r)*64 + d4;
        float4 k2 = *(const float4*)&g_ks[so];
        sKt[d4][64+r]=k2.x; sKt[d4+1][64+r]=k2.y; sKt[d4+2][64+r]=k2.z; sKt[d4+3][64+r]=k2.w;
        float4 v2 = *(const float4*)&g_vs[so];
        sV[64+r][d4]=v2.x; sV[64+r][d4+1]=v2.y; sV[64+r][d4+2]=v2.z; sV[64+r][d4+3]=v2.w;
    }
    __syncthreads();

    const int tx = tid & 15, ty = tid >> 4;
    float acc[4][8] = {};
    for (int d = 0; d < 64; d++) {
        float ar[4];
        #pragma unroll
        for (int i = 0; i < 4; i++) ar[i] = sQ[ty*4+i][d];
        float4 b0 = *(const float4*)&sKt[d][tx*8];
        float4 b1 = *(const float4*)&sKt[d][tx*8+4];
        float br[8] = {b0.x,b0.y,b0.z,b0.w,b1.x,b1.y,b1.z,b1.w};
        #pragma unroll
        for (int i = 0; i < 4; i++)
            #pragma unroll
            for (int j = 0; j < 8; j++)
                acc[i][j] += ar[i] * br[j];
    }
    const bool lastb = (n == NB_ - 1);
    #pragma unroll
    for (int i = 0; i < 4; i++)
        #pragma unroll
        for (int j = 0; j < 8; j++) {
            int q = ty*4+i, jj = tx*8+j;
            float v = acc[i][j] * kSCALE;
            if (lastb && jj >= 64) v = -1e9f;
            sS[q][jj] = v;
        }
    __syncthreads();

    const int warp = tid >> 5, lane = tid & 31;
    for (int r = warp; r < 64; r += 8) {
        float x0=sS[r][lane], x1=sS[r][lane+32], x2=sS[r][lane+64], x3=sS[r][lane+96];
        float m = fmaxf(fmaxf(x0,x1), fmaxf(x2,x3));
        #pragma unroll
        for (int o = 16; o; o >>= 1) m = fmaxf(m, __shfl_xor_sync(0xffffffffu, m, o));
        float e0=expf(x0-m), e1=expf(x1-m), e2=expf(x2-m), e3=expf(x3-m);
        float s = e0+e1+e2+e3;
        #pragma unroll
        for (int o = 16; o; o >>= 1) s += __shfl_xor_sync(0xffffffffu, s, o);
        float inv = 1.f / s;
        sS[r][lane]=e0*inv; sS[r][lane+32]=e1*inv; sS[r][lane+64]=e2*inv; sS[r][lane+96]=e3*inv;
    }
    __syncthreads();

    float o[4][4] = {};
    for (int j = 0; j < 128; j++) {
        float p[4];
        #pragma unroll
        for (int i = 0; i < 4; i++) p[i] = sS[ty*4+i][j];
        float4 vv = *(const float4*)&sV[j][tx*4];
        float vr[4] = {vv.x, vv.y, vv.z, vv.w};
        #pragma unroll
        for (int i = 0; i < 4; i++)
            #pragma unroll
            for (int k = 0; k < 4; k++)
                o[i][k] += p[i] * vr[k];
    }
    #pragma unroll
    for (int i = 0; i < 4; i++) {
        int q = ty*4+i;
        size_t off = ((size_t)(b*L_ + n*64 + q)) * D_ + h*64 + tx*4;
        *(float4*)&g_ctx[off] = make_float4(o[i][0], o[i][1], o[i][2], o[i][3]);
    }
}

// =====================================================================
// launcher
// =====================================================================
extern "C" void kernel_launch(void* const* d_in, const int* in_sizes, int n_in,
                              void* d_out, int out_size)
{
    (void)in_sizes; (void)n_in; (void)out_size;
    const float* x      = (const float*)d_in[0];
    const float* gumbel = (const float*)d_in[1];
    const float* W_qkv  = (const float*)d_in[2];
    const float* b_qkv  = (const float*)d_in[3];
    const float* W_out  = (const float*)d_in[4];
    const float* b_out  = (const float*)d_in[5];
    float* out = (float*)d_out;

    float *qkv_p, *ctx_p;
    uint4 *ah, *al, *ch, *cl, *bh, *bl, *b2h, *b2l;
    cudaGetSymbolAddress((void**)&qkv_p, g_qkv);
    cudaGetSymbolAddress((void**)&ctx_p, g_ctx);
    cudaGetSymbolAddress((void**)&ah,  g_ah4);
    cudaGetSymbolAddress((void**)&al,  g_al4);
    cudaGetSymbolAddress((void**)&ch,  g_ch4);
    cudaGetSymbolAddress((void**)&cl,  g_cl4);
    cudaGetSymbolAddress((void**)&bh,  g_bh4);
    cudaGetSymbolAddress((void**)&bl,  g_bl4);
    cudaGetSymbolAddress((void**)&b2h, g_b2h4);
    cudaGetSymbolAddress((void**)&b2l, g_b2l4);

    const int SMEM_MMA = 2 * STAGE_BYTES_;   // 81920 B double-buffered
    cudaFuncSetAttribute(mma_gemm, cudaFuncAttributeMaxDynamicSharedMemorySize, SMEM_MMA);
    int smem_attn = (64*65 + 64*132 + 128*64 + 64*132) * (int)sizeof(float);
    cudaFuncSetAttribute(attn_kernel, cudaFuncAttributeMaxDynamicSharedMemorySize, smem_attn);

    // 0) precision-split operands
    split_kernel<<<(M_*KDIM_/4 + 255)/256, 256>>>((const float4*)x, (uint2*)ah, (uint2*)al, M_*KDIM_/4);
    tsplit_kernel<<<dim3(QKVROW_/32, KDIM_/32), dim3(32,8)>>>(W_qkv, (__nv_bfloat16*)bh, (__nv_bfloat16*)bl, KDIM_, QKVROW_);
    tsplit_kernel<<<dim3(D_/32, KDIM_/32), dim3(32,8)>>>(W_out, (__nv_bfloat16*)b2h, (__nv_bfloat16*)b2l, KDIM_, D_);

    // 1) qkv projection on tensor cores (mma.sync)
    mma_gemm<<<dim3(QKVROW_/128, M_/128), 256, SMEM_MMA>>>(ah, al, bh, bl, b_qkv, qkv_p, QKVROW_);
    // 2-5) summaries, sinkhorn, sort, attention
    repr_kernel<<<dim3(NB_, BH_), 64>>>();
    sinkhorn_kernel<<<BH_, 256>>>(gumbel);
    sort_kernel<<<dim3(64, BH_), 256>>>();
    attn_kernel<<<dim3(NB_, BH_), 256, smem_attn>>>();
    // 6) output projection on tensor cores
    split_kernel<<<(M_*KDIM_/4 + 255)/256, 256>>>((const float4*)ctx_p, (uint2*)ch, (uint2*)cl, M_*KDIM_/4);
    mma_gemm<<<dim3(D_/128, M_/128), 256, SMEM_MMA>>>(ch, cl, b2h, b2l, b_out, out, D_);
}

// round 17
// speedup vs baseline: 1.8229x; 1.0393x over previous
#include <cuda_runtime.h>
#include <cuda_bf16.h>
#include <cstdint>

// ---------------- problem constants ----------------
#define B_   4
#define L_   4096
#define D_   1024
#define H_   16
#define BS_  64
#define HD_  64
#define NB_  64
#define M_   (B_*L_)      // 16384 rows
#define BH_  (B_*H_)      // 64
#define QKVROW_ 3072      // 3*D
#define KDIM_ 1024

__device__ __constant__ float kSCALE   = 0.125f;          // HD^-0.5
__device__ __constant__ float kINVTEMP = 1.0f/0.7f;

// ---------------- scratch (device globals; no runtime alloc) ----------------
__device__ float g_qkv[M_ * QKVROW_];                 // [B,L,3D]   201 MB
__device__ float g_qr [BH_ * NB_ * HD_];
__device__ float g_kr [BH_ * NB_ * HD_];
__device__ float g_P  [BH_ * NB_ * NB_];
__device__ float g_ks [BH_ * NB_ * BS_ * HD_];        // sorted K
__device__ float g_vs [BH_ * NB_ * BS_ * HD_];        // sorted V

// bf16 split operands (uint4-typed for guaranteed 16B alignment)
__device__ uint4 g_ah4 [M_ * KDIM_ / 8];              // x hi
__device__ uint4 g_al4 [M_ * KDIM_ / 8];              // x lo
__device__ uint4 g_ch4 [M_ * KDIM_ / 8];              // ctx hi (written by attn)
__device__ uint4 g_cl4 [M_ * KDIM_ / 8];              // ctx lo (written by attn)
__device__ uint4 g_bh4 [QKVROW_ * KDIM_ / 8];         // W_qkv^T hi
__device__ uint4 g_bl4 [QKVROW_ * KDIM_ / 8];         // W_qkv^T lo
__device__ uint4 g_b2h4[D_ * KDIM_ / 8];              // W_out^T hi
__device__ uint4 g_b2l4[D_ * KDIM_ / 8];              // W_out^T lo

// =====================================================================
// arch-portable helpers (sm_80+ features only)
// =====================================================================
__device__ __forceinline__ uint32_t smem_u32(const void* p) {
    uint32_t a;
    asm("{ .reg .u64 t; cvta.to.shared.u64 t, %1; cvt.u32.u64 %0, t; }" : "=r"(a) : "l"(p));
    return a;
}
__device__ __forceinline__ void ldsm_x4(uint32_t* r, uint32_t addr) {
    asm volatile("ldmatrix.sync.aligned.m8n8.x4.shared.b16 {%0,%1,%2,%3}, [%4];"
                 : "=r"(r[0]), "=r"(r[1]), "=r"(r[2]), "=r"(r[3]) : "r"(addr));
}
__device__ __forceinline__ void mma_bf16(float* d, const uint32_t* a, uint32_t b0, uint32_t b1) {
    asm volatile("mma.sync.aligned.m16n8k16.row.col.f32.bf16.bf16.f32 "
                 "{%0,%1,%2,%3}, {%4,%5,%6,%7}, {%8,%9}, {%0,%1,%2,%3};"
                 : "+f"(d[0]), "+f"(d[1]), "+f"(d[2]), "+f"(d[3])
                 : "r"(a[0]), "r"(a[1]), "r"(a[2]), "r"(a[3]), "r"(b0), "r"(b1));
}
__device__ __forceinline__ void cp_async16(uint32_t saddr, const void* gptr) {
    asm volatile("cp.async.cg.shared.global [%0], [%1], 16;" :: "r"(saddr), "l"(gptr));
}
#define CP_COMMIT()  asm volatile("cp.async.commit_group;" ::: "memory")
#define CP_WAIT(n)   asm volatile("cp.async.wait_group %0;" :: "n"(n) : "memory")

// packed fp32x2 (SASS FFMA2) — proven 47TF/s path from the R2 kernel
__device__ __forceinline__ unsigned long long ffma2(unsigned long long a,
                                                    unsigned long long b,
                                                    unsigned long long c)
{
    unsigned long long d;
    asm("fma.rn.f32x2 %0, %1, %2, %3;" : "=l"(d) : "l"(a), "l"(b), "l"(c));
    return d;
}
__device__ __forceinline__ unsigned long long pack2(float x, float y)
{
    unsigned long long d;
    asm("mov.b64 %0, {%1, %2};" : "=l"(d) : "f"(x), "f"(y));
    return d;
}
__device__ __forceinline__ float2 unpack2(unsigned long long v)
{
    float2 r;
    asm("mov.b64 {%0, %1}, %2;" : "=f"(r.x), "=f"(r.y) : "l"(v));
    return r;
}

// =====================================================================
// split fp32 -> (hi, lo) bf16.  4 elems/thread, vectorized.
// =====================================================================
__global__ void split_kernel(const float4* __restrict__ src,
                             uint2* __restrict__ hi, uint2* __restrict__ lo, int n4)
{
    int i = blockIdx.x * blockDim.x + threadIdx.x;
    if (i >= n4) return;
    float4 v = src[i];
    float vv[4] = {v.x, v.y, v.z, v.w};
    uint32_t hh[4], ll[4];
    #pragma unroll
    for (int j = 0; j < 4; j++) {
        __nv_bfloat16 h = __float2bfloat16(vv[j]);
        __nv_bfloat16 l = __float2bfloat16(vv[j] - __bfloat162float(h));
        hh[j] = (uint32_t)__bfloat16_as_ushort(h);
        ll[j] = (uint32_t)__bfloat16_as_ushort(l);
    }
    hi[i] = make_uint2(hh[0] | (hh[1] << 16), hh[2] | (hh[3] << 16));
    lo[i] = make_uint2(ll[0] | (ll[1] << 16), ll[2] | (ll[3] << 16));
}

// =====================================================================
// transpose + split: W[K,N] fp32 -> Wt_hi/lo[N,K] bf16
// =====================================================================
__global__ void tsplit_kernel(const float* __restrict__ W,
                              __nv_bfloat16* __restrict__ Th, __nv_bfloat16* __restrict__ Tl,
                              int Kdim, int Ncols)
{
    __shared__ float s[32][33];
    int n0 = blockIdx.x * 32, k0 = blockIdx.y * 32;
    int tx = threadIdx.x, ty = threadIdx.y;          // 32 x 8
    #pragma unroll
    for (int j = 0; j < 4; j++)
        s[ty + 8*j][tx] = W[(size_t)(k0 + ty + 8*j) * Ncols + n0 + tx];
    __syncthreads();
    #pragma unroll
    for (int j = 0; j < 4; j++) {
        float v = s[tx][ty + 8*j];
        __nv_bfloat16 h = __float2bfloat16(v);
        __nv_bfloat16 l = __float2bfloat16(v - __bfloat162float(h));
        size_t o = (size_t)(n0 + ty + 8*j) * Kdim + k0 + tx;
        Th[o] = h; Tl[o] = l;
    }
}

// =====================================================================
// mma.sync split-bf16 GEMM (UNCHANGED — proven 959us/qkv, protect the win)
// =====================================================================
#define TILE_BYTES_  10240                 // 128 * 80
#define STAGE_BYTES_ 40960                 // 4 matrices
__global__ __launch_bounds__(256) void mma_gemm(
    const uint4* __restrict__ Ah4, const uint4* __restrict__ Al4,
    const uint4* __restrict__ Bh4, const uint4* __restrict__ Bl4,
    const float* __restrict__ bias, float* __restrict__ C, int N)
{
    extern __shared__ __align__(16) char smem[];
    const uint32_t sbase = smem_u32(smem);
    const int tid  = threadIdx.x;
    const int lane = tid & 31, wid = tid >> 5;
    const int wm = (wid & 1) * 64;
    const int wn = (wid >> 1) * 32;
    const int m0 = blockIdx.y * 128;
    const int n0 = blockIdx.x * 128;

    float acc[4][4][4] = {};

    #define ISSUE_STAGE(S, BUF) do {                                          \
        uint32_t sb_ = sbase + (BUF) * STAGE_BYTES_;                          \
        _Pragma("unroll")                                                     \
        for (int t = 0; t < 8; t++) {                                         \
            const int mtx = t >> 1;                                           \
            int rem = tid + (t & 1) * 256;                                    \
            int row = rem >> 2, c = rem & 3;                                  \
            const uint4* src = (mtx == 0) ? Ah4 : (mtx == 1) ? Al4            \
                             : (mtx == 2) ? Bh4 : Bl4;                        \
            int rb = (mtx < 2) ? m0 : n0;                                     \
            cp_async16(sb_ + mtx * TILE_BYTES_ + row * 80 + c * 16,           \
                       src + (size_t)(rb + row) * 128 + (S) * 4 + c);         \
        }                                                                     \
        CP_COMMIT();                                                          \
    } while (0)

    ISSUE_STAGE(0, 0);

    for (int s = 0; s < 32; s++) {
        const int buf = s & 1;
        if (s + 1 < 32) { ISSUE_STAGE(s + 1, buf ^ 1); CP_WAIT(1); }
        else            { CP_WAIT(0); }
        __syncthreads();

        const uint32_t sb = sbase + buf * STAGE_BYTES_;
        #pragma unroll
        for (int kt = 0; kt < 2; kt++) {
            const uint32_t lrow = (uint32_t)(lane & 15);
            const uint32_t lcolB = (uint32_t)(kt * 16 + ((lane >> 4) << 3)) * 2;
            uint32_t Ahf[4][4], Alf[4][4];
            #pragma unroll
            for (int mt = 0; mt < 4; mt++) {
                uint32_t off = (wm + mt * 16 + lrow) * 80 + lcolB;
                ldsm_x4(Ahf[mt], sb + 0 * TILE_BYTES_ + off);
                ldsm_x4(Alf[mt], sb + 1 * TILE_BYTES_ + off);
            }
            uint32_t Bhf[2][4], Blf[2][4];
            #pragma unroll
            for (int np = 0; np < 2; np++) {
                uint32_t off = (wn + np * 16 + lrow) * 80 + lcolB;
                ldsm_x4(Bhf[np], sb + 2 * TILE_BYTES_ + off);
                ldsm_x4(Blf[np], sb + 3 * TILE_BYTES_ + off);
            }
            #pragma unroll
            for (int mt = 0; mt < 4; mt++)
                #pragma unroll
                for (int nt = 0; nt < 4; nt++) {
                    const int np = nt >> 1, hi = nt & 1;
                    mma_bf16(acc[mt][nt], Ahf[mt], Bhf[np][hi], Bhf[np][hi + 2]);
                    mma_bf16(acc[mt][nt], Ahf[mt], Blf[np][hi], Blf[np][hi + 2]);
                    mma_bf16(acc[mt][nt], Alf[mt], Bhf[np][hi], Bhf[np][hi + 2]);
                }
        }
        __syncthreads();
    }

    #pragma unroll
    for (int mt = 0; mt < 4; mt++)
        #pragma unroll
        for (int nt = 0; nt < 4; nt++) {
            int row = m0 + wm + mt * 16 + (lane >> 2);
            int col = n0 + wn + nt * 8 + 2 * (lane & 3);
            float2 b2 = *(const float2*)&bias[col];
            float2 o0 = make_float2(acc[mt][nt][0] + b2.x, acc[mt][nt][1] + b2.y);
            float2 o1 = make_float2(acc[mt][nt][2] + b2.x, acc[mt][nt][3] + b2.y);
            *(float2*)&C[(size_t)row * N + col]       = o0;
            *(float2*)&C[(size_t)(row + 8) * N + col] = o1;
        }
}

// =====================================================================
// 2) Block means
// =====================================================================
__global__ void repr_kernel()
{
    int n = blockIdx.x, bh = blockIdx.y;
    int b = bh >> 4, h = bh & 15;
    int d = threadIdx.x;
    const float* base = g_qkv + ((size_t)(b*L_ + n*BS_)) * QKVROW_ + h*64 + d;
    float sq = 0.f, sk = 0.f;
    #pragma unroll 8
    for (int s = 0; s < 64; s++) {
        sq += base[(size_t)s * QKVROW_];
        sk += base[(size_t)s * QKVROW_ + 1024];
    }
    g_qr[((size_t)bh*64 + n)*64 + d] = sq * (1.f/64.f);
    g_kr[((size_t)bh*64 + n)*64 + d] = sk * (1.f/64.f);
}

// =====================================================================
// 3) sim + gumbel + 7 Sinkhorn iterations + exp -> P
// =====================================================================
__global__ __launch_bounds__(256) void sinkhorn_kernel(const float* __restrict__ gumbel)
{
    __shared__ float sQ[64][65], sK[64][65], la[64][65];
    const int bh = blockIdx.x;
    const int tid = threadIdx.x;

    for (int f = tid; f < 1024; f += 256) {
        int r = f >> 4, c4 = (f & 15) * 4;
        float4 q = *(const float4*)&g_qr[((size_t)bh*64 + r)*64 + c4];
        float4 k = *(const float4*)&g_kr[((size_t)bh*64 + r)*64 + c4];
        sQ[r][c4]=q.x; sQ[r][c4+1]=q.y; sQ[r][c4+2]=q.z; sQ[r][c4+3]=q.w;
        sK[r][c4]=k.x; sK[r][c4+1]=k.y; sK[r][c4+2]=k.z; sK[r][c4+3]=k.w;
    }
    __syncthreads();

    const int tx = tid & 15, ty = tid >> 4;
    float acc[4][4] = {};
    for (int d = 0; d < 64; d++) {
        float ar[4], br[4];
        #pragma unroll
        for (int i = 0; i < 4; i++) ar[i] = sQ[ty*4+i][d];
        #pragma unroll
        for (int j = 0; j < 4; j++) br[j] = sK[tx*4+j][d];
        #pragma unroll
        for (int i = 0; i < 4; i++)
            #pragma unroll
            for (int j = 0; j < 4; j++)
                acc[i][j] += ar[i] * br[j];
    }
    #pragma unroll
    for (int i = 0; i < 4; i++)
        #pragma unroll
        for (int j = 0; j < 4; j++) {
            int r = ty*4+i, c = tx*4+j;
            float g = gumbel[((size_t)bh*64 + r)*64 + c];
            la[r][c] = (acc[i][j] * kSCALE + g) * kINVTEMP;
        }
    __syncthreads();

    const int warp = tid >> 5, lane = tid & 31;
    for (int it = 0; it < 7; it++) {
        for (int r = warp; r < 64; r += 8) {
            float a = la[r][lane], b = la[r][lane+32];
            float m = fmaxf(a, b);
            #pragma unroll
            for (int o = 16; o; o >>= 1) m = fmaxf(m, __shfl_xor_sync(0xffffffffu, m, o));
            float s = expf(a - m) + expf(b - m);
            #pragma unroll
            for (int o = 16; o; o >>= 1) s += __shfl_xor_sync(0xffffffffu, s, o);
            float lse = m + logf(s);
            la[r][lane] = a - lse; la[r][lane+32] = b - lse;
        }
        __syncthreads();
        for (int c = warp; c < 64; c += 8) {
            float a = la[lane][c], b = la[lane+32][c];
            float m = fmaxf(a, b);
            #pragma unroll
            for (int o = 16; o; o >>= 1) m = fmaxf(m, __shfl_xor_sync(0xffffffffu, m, o));
            float s = expf(a - m) + expf(b - m);
            #pragma unroll
            for (int o = 16; o; o >>= 1) s += __shfl_xor_sync(0xffffffffu, s, o);
            float lse = m + logf(s);
            la[lane][c] = a - lse; la[lane+32][c] = b - lse;
        }
        __syncthreads();
    }
    for (int f = tid; f < 4096; f += 256)
        g_P[(size_t)bh*4096 + f] = expf(la[f >> 6][f & 63]);
}

// =====================================================================
// 4) Soft block-sort — inner product on FFMA2 (halved fma-pipe pressure)
// =====================================================================
__global__ __launch_bounds__(256) void sort_kernel()
{
    __shared__ float sP[64][65], sK[64][68], sV[64][68];
    const int fc = blockIdx.x, bh = blockIdx.y;
    const int b = bh >> 4, h = bh & 15;
    const int tid = threadIdx.x;

    for (int f = tid; f < 1024; f += 256) {
        int r = f >> 4, c4 = (f & 15) * 4;
        float4 p = *(const float4*)&g_P[(size_t)bh*4096 + r*64 + c4];
        sP[r][c4]=p.x; sP[r][c4+1]=p.y; sP[r][c4+2]=p.z; sP[r][c4+3]=p.w;
        const float* src = g_qkv + ((size_t)(b*L_ + r*64 + fc)) * QKVROW_ + 1024 + h*64 + c4;
        float4 k = *(const float4*)src;
        sK[r][c4]=k.x; sK[r][c4+1]=k.y; sK[r][c4+2]=k.z; sK[r][c4+3]=k.w;
        float4 v = *(const float4*)(src + 1024);
        sV[r][c4]=v.x; sV[r][c4+1]=v.y; sV[r][c4+2]=v.z; sV[r][c4+3]=v.w;
    }
    __syncthreads();

    const int tx = tid & 15, ty = tid >> 4;
    unsigned long long aK2[4][2] = {}, aV2[4][2] = {};
    for (int m = 0; m < 64; m++) {
        unsigned long long pd[4];
        #pragma unroll
        for (int i = 0; i < 4; i++) { float p = sP[ty*4+i][m]; pd[i] = pack2(p, p); }
        float4 kk = *(const float4*)&sK[m][tx*4];
        float4 vv = *(const float4*)&sV[m][tx*4];
        unsigned long long kp[2] = {pack2(kk.x, kk.y), pack2(kk.z, kk.w)};
        unsigned long long vp[2] = {pack2(vv.x, vv.y), pack2(vv.z, vv.w)};
        #pragma unroll
        for (int i = 0; i < 4; i++)
            #pragma unroll
            for (int k = 0; k < 2; k++) {
                aK2[i][k] = ffma2(pd[i], kp[k], aK2[i][k]);
                aV2[i][k] = ffma2(pd[i], vp[k], aV2[i][k]);
            }
    }
    #pragma unroll
    for (int i = 0; i < 4; i++) {
        int n = ty*4+i;
        size_t off = (((size_t)bh*64 + n)*64 + fc)*64 + tx*4;
        float2 k0 = unpack2(aK2[i][0]), k1 = unpack2(aK2[i][1]);
        float2 v0 = unpack2(aV2[i][0]), v1 = unpack2(aV2[i][1]);
        *(float4*)&g_ks[off] = make_float4(k0.x, k0.y, k1.x, k1.y);
        *(float4*)&g_vs[off] = make_float4(v0.x, v0.y, v1.x, v1.y);
    }
}

// =====================================================================
// 5) Local block attention — FFMA2 inner loops + fused bf16 split output
//    (writes g_ch4/g_cl4 directly; g_ctx and the extra split launch gone)
// =====================================================================
__global__ __launch_bounds__(256) void attn_kernel()
{
    extern __shared__ float sm[];
    float (*sQ)[65]   = (float(*)[65])  sm;
    float (*sKt)[132] = (float(*)[132]) (sm + 64*65);
    float (*sV)[64]   = (float(*)[64])  (sm + 64*65 + 64*132);
    float (*sS)[132]  = (float(*)[132]) (sm + 64*65 + 64*132 + 128*64);

    const int n = blockIdx.x, bh = blockIdx.y;
    const int b = bh >> 4, h = bh & 15;
    const int tid = threadIdx.x;
    const int n1 = (n + 1) & 63;

    for (int f = tid; f < 1024; f += 256) {
        int r = f >> 4, d4 = (f & 15) * 4;
        const float* src = g_qkv + ((size_t)(b*L_ + n*64 + r)) * QKVROW_ + h*64 + d4;
        float4 q = *(const float4*)src;
        sQ[r][d4]=q.x; sQ[r][d4+1]=q.y; sQ[r][d4+2]=q.z; sQ[r][d4+3]=q.w;
        float4 k = *(const float4*)(src + 1024);
        sKt[d4][r]=k.x; sKt[d4+1][r]=k.y; sKt[d4+2][r]=k.z; sKt[d4+3][r]=k.w;
        float4 v = *(const float4*)(src + 2048);
        sV[r][d4]=v.x; sV[r][d4+1]=v.y; sV[r][d4+2]=v.z; sV[r][d4+3]=v.w;
        size_t so = (((size_t)bh*64 + n1)*64 + r)*64 + d4;
        float4 k2 = *(const float4*)&g_ks[so];
        sKt[d4][64+r]=k2.x; sKt[d4+1][64+r]=k2.y; sKt[d4+2][64+r]=k2.z; sKt[d4+3][64+r]=k2.w;
        float4 v2 = *(const float4*)&g_vs[so];
        sV[64+r][d4]=v2.x; sV[64+r][d4+1]=v2.y; sV[64+r][d4+2]=v2.z; sV[64+r][d4+3]=v2.w;
    }
    __syncthreads();

    const int tx = tid & 15, ty = tid >> 4;
    // scores: q-tile 4 (ty), j-tile 8 as 4 packed pairs (tx)
    unsigned long long acc2[4][4] = {};
    for (int d = 0; d < 64; d++) {
        unsigned long long ad[4];
        #pragma unroll
        for (int i = 0; i < 4; i++) { float a = sQ[ty*4+i][d]; ad[i] = pack2(a, a); }
        float4 b0 = *(const float4*)&sKt[d][tx*8];
        float4 b1 = *(const float4*)&sKt[d][tx*8+4];
        unsigned long long bp[4] = {pack2(b0.x,b0.y), pack2(b0.z,b0.w),
                                    pack2(b1.x,b1.y), pack2(b1.z,b1.w)};
        #pragma unroll
        for (int i = 0; i < 4; i++)
            #pragma unroll
            for (int p = 0; p < 4; p++)
                acc2[i][p] = ffma2(ad[i], bp[p], acc2[i][p]);
    }
    const bool lastb = (n == NB_ - 1);
    const bool maskme = lastb && (tx >= 8);   // cols tx*8.. >= 64
    #pragma unroll
    for (int i = 0; i < 4; i++)
        #pragma unroll
        for (int p = 0; p < 4; p++) {
            int q = ty*4+i, jj = tx*8 + 2*p;
            float2 r = unpack2(acc2[i][p]);
            float v0 = maskme ? -1e9f : r.x * kSCALE;
            float v1 = maskme ? -1e9f : r.y * kSCALE;
            sS[q][jj] = v0; sS[q][jj+1] = v1;
        }
    __syncthreads();

    const int warp = tid >> 5, lane = tid & 31;
    for (int r = warp; r < 64; r += 8) {
        float x0=sS[r][lane], x1=sS[r][lane+32], x2=sS[r][lane+64], x3=sS[r][lane+96];
        float m = fmaxf(fmaxf(x0,x1), fmaxf(x2,x3));
        #pragma unroll
        for (int o = 16; o; o >>= 1) m = fmaxf(m, __shfl_xor_sync(0xffffffffu, m, o));
        float e0=expf(x0-m), e1=expf(x1-m), e2=expf(x2-m), e3=expf(x3-m);
        float s = e0+e1+e2+e3;
        #pragma unroll
        for (int o = 16; o; o >>= 1) s += __shfl_xor_sync(0xffffffffu, s, o);
        float inv = 1.f / s;
        sS[r][lane]=e0*inv; sS[r][lane+32]=e1*inv; sS[r][lane+64]=e2*inv; sS[r][lane+96]=e3*inv;
    }
    __syncthreads();

    // out = P @ V : q-tile 4 (ty), d-tile 4 as 2 packed pairs (tx)
    unsigned long long o2[4][2] = {};
    for (int j = 0; j < 128; j++) {
        unsigned long long pd[4];
        #pragma unroll
        for (int i = 0; i < 4; i++) { float p = sS[ty*4+i][j]; pd[i] = pack2(p, p); }
        float4 vv = *(const float4*)&sV[j][tx*4];
        unsigned long long vp[2] = {pack2(vv.x, vv.y), pack2(vv.z, vv.w)};
        #pragma unroll
        for (int i = 0; i < 4; i++)
            #pragma unroll
            for (int k = 0; k < 2; k++)
                o2[i][k] = ffma2(pd[i], vp[k], o2[i][k]);
    }
    // fused epilogue: bf16 hi/lo split written straight to out-proj operands
    unsigned short* chp = (unsigned short*)g_ch4;
    unsigned short* clp = (unsigned short*)g_cl4;
    #pragma unroll
    for (int i = 0; i < 4; i++) {
        int q = ty*4+i;
        float2 oa = unpack2(o2[i][0]), ob = unpack2(o2[i][1]);
        float of[4] = {oa.x, oa.y, ob.x, ob.y};
        uint32_t hh[4], ll[4];
        #pragma unroll
        for (int k = 0; k < 4; k++) {
            __nv_bfloat16 hv = __float2bfloat16(of[k]);
            __nv_bfloat16 lv = __float2bfloat16(of[k] - __bfloat162float(hv));
            hh[k] = (uint32_t)__bfloat16_as_ushort(hv);
            ll[k] = (uint32_t)__bfloat16_as_ushort(lv);
        }
        size_t eoff = ((size_t)(b*L_ + n*64 + q)) * D_ + h*64 + tx*4;
        *(uint2*)(chp + eoff) = make_uint2(hh[0] | (hh[1] << 16), hh[2] | (hh[3] << 16));
        *(uint2*)(clp + eoff) = make_uint2(ll[0] | (ll[1] << 16), ll[2] | (ll[3] << 16));
    }
}

// =====================================================================
// launcher
// =====================================================================
extern "C" void kernel_launch(void* const* d_in, const int* in_sizes, int n_in,
                              void* d_out, int out_size)
{
    (void)in_sizes; (void)n_in; (void)out_size;
    const float* x      = (const float*)d_in[0];
    const float* gumbel = (const float*)d_in[1];
    const float* W_qkv  = (const float*)d_in[2];
    const float* b_qkv  = (const float*)d_in[3];
    const float* W_out  = (const float*)d_in[4];
    const float* b_out  = (const float*)d_in[5];
    float* out = (float*)d_out;

    float* qkv_p;
    uint4 *ah, *al, *ch, *cl, *bh, *bl, *b2h, *b2l;
    cudaGetSymbolAddress((void**)&qkv_p, g_qkv);
    cudaGetSymbolAddress((void**)&ah,  g_ah4);
    cudaGetSymbolAddress((void**)&al,  g_al4);
    cudaGetSymbolAddress((void**)&ch,  g_ch4);
    cudaGetSymbolAddress((void**)&cl,  g_cl4);
    cudaGetSymbolAddress((void**)&bh,  g_bh4);
    cudaGetSymbolAddress((void**)&bl,  g_bl4);
    cudaGetSymbolAddress((void**)&b2h, g_b2h4);
    cudaGetSymbolAddress((void**)&b2l, g_b2l4);

    const int SMEM_MMA = 2 * STAGE_BYTES_;   // 81920 B double-buffered
    cudaFuncSetAttribute(mma_gemm, cudaFuncAttributeMaxDynamicSharedMemorySize, SMEM_MMA);
    int smem_attn = (64*65 + 64*132 + 128*64 + 64*132) * (int)sizeof(float);
    cudaFuncSetAttribute(attn_kernel, cudaFuncAttributeMaxDynamicSharedMemorySize, smem_attn);

    // 0) precision-split operands
    split_kernel<<<(M_*KDIM_/4 + 255)/256, 256>>>((const float4*)x, (uint2*)ah, (uint2*)al, M_*KDIM_/4);
    tsplit_kernel<<<dim3(QKVROW_/32, KDIM_/32), dim3(32,8)>>>(W_qkv, (__nv_bfloat16*)bh, (__nv_bfloat16*)bl, KDIM_, QKVROW_);
    tsplit_kernel<<<dim3(D_/32, KDIM_/32), dim3(32,8)>>>(W_out, (__nv_bfloat16*)b2h, (__nv_bfloat16*)b2l, KDIM_, D_);

    // 1) qkv projection on tensor cores (mma.sync)
    mma_gemm<<<dim3(QKVROW_/128, M_/128), 256, SMEM_MMA>>>(ah, al, bh, bl, b_qkv, qkv_p, QKVROW_);
    // 2-5) summaries, sinkhorn, sort, attention (attn writes ch/cl directly)
    repr_kernel<<<dim3(NB_, BH_), 64>>>();
    sinkhorn_kernel<<<BH_, 256>>>(gumbel);
    sort_kernel<<<dim3(64, BH_), 256>>>();
    attn_kernel<<<dim3(NB_, BH_), 256, smem_attn>>>();
    // 6) output projection on tensor cores
    mma_gemm<<<dim3(D_/128, M_/128), 256, SMEM_MMA>>>(ch, cl, b2h, b2l, b_out, out, D_);
}